// round 1
// baseline (speedup 1.0000x reference)
#include <cuda_runtime.h>
#include <math.h>

#define HIDDEN 2048
#define NH 16
#define NKV 4
#define HD 128
#define KVD 512
#define BATCH 2
#define SEQ 2048
#define MTOT (BATCH*SEQ)   // 4096

// ---------------- scratch (static device globals; no allocs allowed) -------
__device__ float g_q [(size_t)MTOT * HIDDEN];  // 32 MB
__device__ float g_k [(size_t)MTOT * KVD];     // 8 MB
__device__ float g_v [(size_t)MTOT * KVD];     // 8 MB
__device__ float g_ao[(size_t)MTOT * HIDDEN];  // 32 MB

// ---------------- SGEMM: C[M,N] = A[M,K] * W[N,K]^T  (both row-major) ------
#define BM 128
#define BN 128
#define BKK 16
#define TM 8
#define TN 8

__global__ __launch_bounds__(256) void sgemm_nt(
    const float* __restrict__ A, const float* __restrict__ W,
    float* __restrict__ C, int M, int N, int K)
{
    __shared__ float As[BKK][BM];
    __shared__ float Ws[BKK][BN];
    const int bx = blockIdx.x, by = blockIdx.y;
    const int tid = threadIdx.x;
    const int tx = tid & 15, ty = tid >> 4;
    const int rowA0 = by * BM, colW0 = bx * BN;

    float acc[TM][TN];
    #pragma unroll
    for (int i = 0; i < TM; i++)
        #pragma unroll
        for (int j = 0; j < TN; j++) acc[i][j] = 0.f;

    for (int k0 = 0; k0 < K; k0 += BKK) {
        // load A tile (transposed into smem): 128 rows x 16 k
        #pragma unroll
        for (int it = 0; it < 2; it++) {
            int idx = tid + it * 256;      // float4 index, 512 total
            int m  = idx >> 2;             // 4 float4 per row
            int kq = idx & 3;
            float4 v4 = *(const float4*)(A + (size_t)(rowA0 + m) * K + k0 + kq * 4);
            As[kq*4+0][m] = v4.x; As[kq*4+1][m] = v4.y;
            As[kq*4+2][m] = v4.z; As[kq*4+3][m] = v4.w;
        }
        #pragma unroll
        for (int it = 0; it < 2; it++) {
            int idx = tid + it * 256;
            int n  = idx >> 2;
            int kq = idx & 3;
            float4 v4 = *(const float4*)(W + (size_t)(colW0 + n) * K + k0 + kq * 4);
            Ws[kq*4+0][n] = v4.x; Ws[kq*4+1][n] = v4.y;
            Ws[kq*4+2][n] = v4.z; Ws[kq*4+3][n] = v4.w;
        }
        __syncthreads();

        #pragma unroll
        for (int kk = 0; kk < BKK; kk++) {
            float ra[TM], rw[TN];
            *(float4*)&ra[0] = *(const float4*)&As[kk][ty*TM];
            *(float4*)&ra[4] = *(const float4*)&As[kk][ty*TM+4];
            *(float4*)&rw[0] = *(const float4*)&Ws[kk][tx*TN];
            *(float4*)&rw[4] = *(const float4*)&Ws[kk][tx*TN+4];
            #pragma unroll
            for (int i = 0; i < TM; i++)
                #pragma unroll
                for (int j = 0; j < TN; j++)
                    acc[i][j] = fmaf(ra[i], rw[j], acc[i][j]);
        }
        __syncthreads();
    }

    #pragma unroll
    for (int i = 0; i < TM; i++) {
        float4* cp = (float4*)(C + (size_t)(rowA0 + ty*TM + i) * N + colW0 + tx*TN);
        cp[0] = make_float4(acc[i][0], acc[i][1], acc[i][2], acc[i][3]);
        cp[1] = make_float4(acc[i][4], acc[i][5], acc[i][6], acc[i][7]);
    }
}

// ---------------- RoPE (in-place on q [MTOT,2048] and k [MTOT,512]) --------
__global__ void rope_kernel(float* __restrict__ q, float* __restrict__ k)
{
    const int bs  = blockIdx.x;        // 0..MTOT-1
    const int pos = bs % SEQ;
    const int i   = threadIdx.x;       // 0..63 (pair index)
    float inv = powf(10000.0f, -(float)i / 64.0f);
    float ang = (float)pos * inv;
    float s, c;
    sincosf(ang, &s, &c);

    #pragma unroll
    for (int h = 0; h < NH; h++) {
        float* p = q + (size_t)bs * HIDDEN + h * HD;
        float a = p[i], b2 = p[i + 64];
        p[i]      = a * c - b2 * s;
        p[i + 64] = b2 * c + a * s;
    }
    #pragma unroll
    for (int h = 0; h < NKV; h++) {
        float* p = k + (size_t)bs * KVD + h * HD;
        float a = p[i], b2 = p[i + 64];
        p[i]      = a * c - b2 * s;
        p[i + 64] = b2 * c + a * s;
    }
}

// ---------------- Flash attention (causal, GQA), fp32 ----------------------
#define BQ 64
#define BKV 64

struct AttnSmem {
    float Qt[HD][BQ];      // Q transposed: [d][row]
    float Kt[HD][BKV];     // K transposed: [d][col]
    float V [BKV][HD];
    float P [BQ][BKV];
    float Mx[BQ];
    float L [BQ];
    float Alpha[BQ];
    int   Msk[BKV];
};

__global__ __launch_bounds__(256) void attn_kernel(
    const float* __restrict__ q, const float* __restrict__ k,
    const float* __restrict__ v, const int* __restrict__ amask,
    float* __restrict__ ao)
{
    extern __shared__ char smraw[];
    AttnSmem* S = reinterpret_cast<AttnSmem*>(smraw);

    const int qb = blockIdx.x;   // query tile
    const int h  = blockIdx.y;   // q head
    const int b  = blockIdx.z;   // batch
    const int kvh = h / (NH / NKV);
    const int tid = threadIdx.x;
    const int tx = tid & 15, ty = tid >> 4;

    // load Q tile, transposed
    for (int idx = tid; idx < BQ * HD / 4; idx += 256) {
        int r = idx >> 5, dq = idx & 31;   // HD/4 = 32 float4 per row
        float4 v4 = *(const float4*)(q + (size_t)(b * SEQ + qb * BQ + r) * HIDDEN + h * HD + dq * 4);
        S->Qt[dq*4+0][r] = v4.x; S->Qt[dq*4+1][r] = v4.y;
        S->Qt[dq*4+2][r] = v4.z; S->Qt[dq*4+3][r] = v4.w;
    }
    if (tid < BQ) { S->Mx[tid] = -1e30f; S->L[tid] = 0.f; }
    __syncthreads();

    float accO[4][8];
    #pragma unroll
    for (int i = 0; i < 4; i++)
        #pragma unroll
        for (int j = 0; j < 8; j++) accO[i][j] = 0.f;

    const float scale = 0.08838834764831845f;  // 1/sqrt(128)
    const int nkv = qb + 1;                    // causal: kv tiles up to diag

    for (int kb = 0; kb < nkv; kb++) {
        // load K (transposed) and V tiles
        for (int idx = tid; idx < BKV * HD / 4; idx += 256) {
            int r = idx >> 5, dq = idx & 31;
            size_t base = (size_t)(b * SEQ + kb * BKV + r) * KVD + kvh * HD + dq * 4;
            float4 k4 = *(const float4*)(k + base);
            S->Kt[dq*4+0][r] = k4.x; S->Kt[dq*4+1][r] = k4.y;
            S->Kt[dq*4+2][r] = k4.z; S->Kt[dq*4+3][r] = k4.w;
            *(float4*)&S->V[r][dq*4] = *(const float4*)(v + base);
        }
        if (tid < BKV) S->Msk[tid] = amask[b * SEQ + kb * BKV + tid];
        __syncthreads();

        // S = Q K^T : each thread 4 rows x 4 cols
        float sc[4][4];
        #pragma unroll
        for (int i = 0; i < 4; i++)
            #pragma unroll
            for (int j = 0; j < 4; j++) sc[i][j] = 0.f;

        for (int d = 0; d < HD; d++) {
            float4 rq = *(const float4*)&S->Qt[d][ty * 4];
            float4 rk = *(const float4*)&S->Kt[d][tx * 4];
            float ra[4] = {rq.x, rq.y, rq.z, rq.w};
            float rb[4] = {rk.x, rk.y, rk.z, rk.w};
            #pragma unroll
            for (int i = 0; i < 4; i++)
                #pragma unroll
                for (int j = 0; j < 4; j++)
                    sc[i][j] = fmaf(ra[i], rb[j], sc[i][j]);
        }

        // scale + mask, stage scores in smem
        #pragma unroll
        for (int i = 0; i < 4; i++) {
            int rg = qb * BQ + ty * 4 + i;
            #pragma unroll
            for (int j = 0; j < 4; j++) {
                int cl = tx * 4 + j;
                int cg = kb * BKV + cl;
                float val = sc[i][j] * scale;
                if (cg > rg || S->Msk[cl] == 0) val = -1e30f;
                S->P[ty*4+i][cl] = val;
            }
        }
        __syncthreads();

        // online softmax: one thread per query row
        if (tid < BQ) {
            float mo = S->Mx[tid], m = mo;
            #pragma unroll 8
            for (int c = 0; c < BKV; c++) m = fmaxf(m, S->P[tid][c]);
            float ls = 0.f;
            #pragma unroll 8
            for (int c = 0; c < BKV; c++) {
                float p = __expf(S->P[tid][c] - m);
                S->P[tid][c] = p;
                ls += p;
            }
            float al = __expf(mo - m);
            S->Alpha[tid] = al;
            S->L[tid] = S->L[tid] * al + ls;
            S->Mx[tid] = m;
        }
        __syncthreads();

        // rescale accumulators, then O += P @ V (4 rows x 8 cols per thread)
        float al[4];
        #pragma unroll
        for (int i = 0; i < 4; i++) al[i] = S->Alpha[ty * 4 + i];
        #pragma unroll
        for (int i = 0; i < 4; i++)
            #pragma unroll
            for (int j = 0; j < 8; j++) accO[i][j] *= al[i];

        for (int kk = 0; kk < BKV; kk++) {
            float pv[4];
            #pragma unroll
            for (int i = 0; i < 4; i++) pv[i] = S->P[ty*4+i][kk];
            float4 v0 = *(const float4*)&S->V[kk][tx*8];
            float4 v1 = *(const float4*)&S->V[kk][tx*8+4];
            float vv[8] = {v0.x, v0.y, v0.z, v0.w, v1.x, v1.y, v1.z, v1.w};
            #pragma unroll
            for (int i = 0; i < 4; i++)
                #pragma unroll
                for (int j = 0; j < 8; j++)
                    accO[i][j] = fmaf(pv[i], vv[j], accO[i][j]);
        }
        __syncthreads();
    }

    // epilogue: normalize and write to [b, s, h*HD + d] layout
    #pragma unroll
    for (int i = 0; i < 4; i++) {
        int r = ty * 4 + i;
        float invl = 1.0f / S->L[r];
        float4 o0 = make_float4(accO[i][0]*invl, accO[i][1]*invl, accO[i][2]*invl, accO[i][3]*invl);
        float4 o1 = make_float4(accO[i][4]*invl, accO[i][5]*invl, accO[i][6]*invl, accO[i][7]*invl);
        float4* op = (float4*)(ao + (size_t)(b * SEQ + qb * BQ + r) * HIDDEN + h * HD + tx * 8);
        op[0] = o0;
        op[1] = o1;
    }
}

// ---------------- launch ----------------------------------------------------
extern "C" void kernel_launch(void* const* d_in, const int* in_sizes, int n_in,
                              void* d_out, int out_size)
{
    const float* hs    = (const float*)d_in[0];
    const int*   amask = (const int*)  d_in[1];
    const float* wq    = (const float*)d_in[2];
    const float* wk    = (const float*)d_in[3];
    const float* wv    = (const float*)d_in[4];
    const float* wo    = (const float*)d_in[5];
    float* out = (float*)d_out;

    float *dq, *dk, *dv, *dao;
    cudaGetSymbolAddress((void**)&dq,  g_q);
    cudaGetSymbolAddress((void**)&dk,  g_k);
    cudaGetSymbolAddress((void**)&dv,  g_v);
    cudaGetSymbolAddress((void**)&dao, g_ao);

    // projections
    sgemm_nt<<<dim3(HIDDEN / BN, MTOT / BM), 256>>>(hs, wq, dq, MTOT, HIDDEN, HIDDEN);
    sgemm_nt<<<dim3(KVD    / BN, MTOT / BM), 256>>>(hs, wk, dk, MTOT, KVD,    HIDDEN);
    sgemm_nt<<<dim3(KVD    / BN, MTOT / BM), 256>>>(hs, wv, dv, MTOT, KVD,    HIDDEN);

    // RoPE on q and k
    rope_kernel<<<MTOT, 64>>>(dq, dk);

    // flash attention
    size_t smb = sizeof(AttnSmem);
    cudaFuncSetAttribute(attn_kernel, cudaFuncAttributeMaxDynamicSharedMemorySize, (int)smb);
    attn_kernel<<<dim3(SEQ / BQ, NH, BATCH), 256, smb>>>(dq, dk, dv, amask, dao);

    // output projection
    sgemm_nt<<<dim3(HIDDEN / BN, MTOT / BM), 256>>>(dao, wo, out, MTOT, HIDDEN, HIDDEN);
}

// round 3
// speedup vs baseline: 1.1904x; 1.1904x over previous
#include <cuda_runtime.h>
#include <math.h>
#include <stdint.h>

#define HIDDEN 2048
#define NH 16
#define NKV 4
#define HD 128
#define KVD 512
#define BATCH 2
#define SEQ 2048
#define MTOT (BATCH*SEQ)   // 4096

// ---------------- scratch (static device globals; no allocs allowed) -------
__device__ float g_q [(size_t)MTOT * HIDDEN];  // 32 MB
__device__ float g_k [(size_t)MTOT * KVD];     // 8 MB
__device__ float g_v [(size_t)MTOT * KVD];     // 8 MB
__device__ float g_ao[(size_t)MTOT * HIDDEN];  // 32 MB

// ============================================================================
// 3xTF32 tensor-core GEMM: C[M,N] = A[M,K] * W[N,K]^T  (row-major A, W)
// Markidis split: x = hi + lo, acc += hi*hi + hi*lo + lo*hi  (~fp32 accuracy)
// 128x128x32 block tile, 8 warps (4x2), warp tile 32x64, mma.m16n8k8 tf32
// ============================================================================
#define GBM 128
#define GBN 128
#define GBK 32
#define GPAD 4
#define GLDW (GBK + GPAD)   // 36 floats per smem row

__device__ __forceinline__ void cp_async16(void* dst, const void* src) {
    uint32_t d = (uint32_t)__cvta_generic_to_shared(dst);
    asm volatile("cp.async.cg.shared.global [%0], [%1], 16;\n" :: "r"(d), "l"(src));
}
__device__ __forceinline__ void cp_commit() {
    asm volatile("cp.async.commit_group;\n");
}
__device__ __forceinline__ void cp_wait1() {
    asm volatile("cp.async.wait_group 1;\n");
}
__device__ __forceinline__ void cp_wait0() {
    asm volatile("cp.async.wait_group 0;\n");
}

__device__ __forceinline__ uint32_t f2tf32(float x) {
    uint32_t r;
    asm("cvt.rna.tf32.f32 %0, %1;" : "=r"(r) : "f"(x));
    return r;
}

__device__ __forceinline__ void mma_tf32(float* d, const uint32_t* a, const uint32_t* b) {
    asm volatile(
        "mma.sync.aligned.m16n8k8.row.col.f32.tf32.tf32.f32 "
        "{%0,%1,%2,%3}, {%4,%5,%6,%7}, {%8,%9}, {%0,%1,%2,%3};"
        : "+f"(d[0]), "+f"(d[1]), "+f"(d[2]), "+f"(d[3])
        : "r"(a[0]), "r"(a[1]), "r"(a[2]), "r"(a[3]),
          "r"(b[0]), "r"(b[1]));
}

__global__ __launch_bounds__(256) void gemm_3xtf32(
    const float* __restrict__ A, const float* __restrict__ W,
    float* __restrict__ C, int M, int N, int K)
{
    extern __shared__ float sm[];
    float* As = sm;                              // 2*128*36
    float* Ws = sm + 2 * GBM * GLDW;             // 2*128*36

    const int tid  = threadIdx.x;
    const int warp = tid >> 5, lane = tid & 31;
    const int wr = warp >> 1, wc = warp & 1;     // warp grid 4x2
    const int rowA0 = blockIdx.y * GBM;
    const int colW0 = blockIdx.x * GBN;

    const int nTiles = K / GBK;

    auto loadTile = [&](int t, int buf) {
        const float* Ab = A + (size_t)rowA0 * K + t * GBK;
        const float* Wb = W + (size_t)colW0 * K + t * GBK;
        float* Ad = As + buf * GBM * GLDW;
        float* Wd = Ws + buf * GBN * GLDW;
        #pragma unroll
        for (int i = 0; i < 4; i++) {
            int chunk = tid + i * 256;       // 0..1023
            int r  = chunk >> 3;             // 8 float4 per row of 32
            int kq = chunk & 7;
            cp_async16(Ad + r * GLDW + kq * 4, Ab + (size_t)r * K + kq * 4);
            cp_async16(Wd + r * GLDW + kq * 4, Wb + (size_t)r * K + kq * 4);
        }
        cp_commit();
    };

    float acc[2][8][4];
    #pragma unroll
    for (int mi = 0; mi < 2; mi++)
        #pragma unroll
        for (int ni = 0; ni < 8; ni++)
            #pragma unroll
            for (int r = 0; r < 4; r++) acc[mi][ni][r] = 0.f;

    loadTile(0, 0);

    for (int t = 0; t < nTiles; t++) {
        int buf = t & 1;
        if (t + 1 < nTiles) {
            loadTile(t + 1, buf ^ 1);
            cp_wait1();
        } else {
            cp_wait0();
        }
        __syncthreads();

        const float* Ab = As + buf * GBM * GLDW;
        const float* Wb = Ws + buf * GBN * GLDW;
        const int r0 = wr * 32 + (lane >> 2);
        const int n0 = wc * 64 + (lane >> 2);

        #pragma unroll
        for (int kk = 0; kk < 4; kk++) {
            const int c0 = kk * 8 + (lane & 3);

            uint32_t ah[2][4], al[2][4];
            #pragma unroll
            for (int mi = 0; mi < 2; mi++) {
                int r = r0 + mi * 16;
                float x0 = Ab[(r    ) * GLDW + c0    ];
                float x1 = Ab[(r + 8) * GLDW + c0    ];
                float x2 = Ab[(r    ) * GLDW + c0 + 4];
                float x3 = Ab[(r + 8) * GLDW + c0 + 4];
                ah[mi][0] = f2tf32(x0); al[mi][0] = f2tf32(x0 - __uint_as_float(ah[mi][0]));
                ah[mi][1] = f2tf32(x1); al[mi][1] = f2tf32(x1 - __uint_as_float(ah[mi][1]));
                ah[mi][2] = f2tf32(x2); al[mi][2] = f2tf32(x2 - __uint_as_float(ah[mi][2]));
                ah[mi][3] = f2tf32(x3); al[mi][3] = f2tf32(x3 - __uint_as_float(ah[mi][3]));
            }
            uint32_t bh[8][2], bl[8][2];
            #pragma unroll
            for (int ni = 0; ni < 8; ni++) {
                int n = n0 + ni * 8;
                float y0 = Wb[n * GLDW + c0    ];
                float y1 = Wb[n * GLDW + c0 + 4];
                bh[ni][0] = f2tf32(y0); bl[ni][0] = f2tf32(y0 - __uint_as_float(bh[ni][0]));
                bh[ni][1] = f2tf32(y1); bl[ni][1] = f2tf32(y1 - __uint_as_float(bh[ni][1]));
            }
            #pragma unroll
            for (int mi = 0; mi < 2; mi++)
                #pragma unroll
                for (int ni = 0; ni < 8; ni++) {
                    mma_tf32(acc[mi][ni], al[mi], bh[ni]);   // lo*hi
                    mma_tf32(acc[mi][ni], ah[mi], bl[ni]);   // hi*lo
                    mma_tf32(acc[mi][ni], ah[mi], bh[ni]);   // hi*hi
                }
        }
        __syncthreads();
    }

    #pragma unroll
    for (int mi = 0; mi < 2; mi++) {
        #pragma unroll
        for (int ni = 0; ni < 8; ni++) {
            int row = rowA0 + wr * 32 + mi * 16 + (lane >> 2);
            int col = colW0 + wc * 64 + ni * 8 + 2 * (lane & 3);
            *(float2*)(C + (size_t)row * N + col) =
                make_float2(acc[mi][ni][0], acc[mi][ni][1]);
            *(float2*)(C + (size_t)(row + 8) * N + col) =
                make_float2(acc[mi][ni][2], acc[mi][ni][3]);
        }
    }
}

// ---------------- RoPE (in-place on q [MTOT,2048] and k [MTOT,512]) --------
__global__ void rope_kernel(float* __restrict__ q, float* __restrict__ k)
{
    const int bs  = blockIdx.x;        // 0..MTOT-1
    const int pos = bs % SEQ;
    const int i   = threadIdx.x;       // 0..63 (pair index)
    float inv = powf(10000.0f, -(float)i / 64.0f);
    float ang = (float)pos * inv;
    float s, c;
    sincosf(ang, &s, &c);

    #pragma unroll
    for (int h = 0; h < NH; h++) {
        float* p = q + (size_t)bs * HIDDEN + h * HD;
        float a = p[i], b2 = p[i + 64];
        p[i]      = a * c - b2 * s;
        p[i + 64] = b2 * c + a * s;
    }
    #pragma unroll
    for (int h = 0; h < NKV; h++) {
        float* p = k + (size_t)bs * KVD + h * HD;
        float a = p[i], b2 = p[i + 64];
        p[i]      = a * c - b2 * s;
        p[i + 64] = b2 * c + a * s;
    }
}

// ---------------- Flash attention (causal, GQA), fp32 ----------------------
#define BQ 64
#define BKV 64

struct AttnSmem {
    float Qt[HD][BQ];      // Q transposed: [d][row]
    float Kt[HD][BKV];     // K transposed: [d][col]
    float V [BKV][HD];
    float P [BQ][BKV];
    float Mx[BQ];
    float L [BQ];
    float Alpha[BQ];
    int   Msk[BKV];
};

__global__ __launch_bounds__(256) void attn_kernel(
    const float* __restrict__ q, const float* __restrict__ k,
    const float* __restrict__ v, const int* __restrict__ amask,
    float* __restrict__ ao)
{
    extern __shared__ char smraw[];
    AttnSmem* S = reinterpret_cast<AttnSmem*>(smraw);

    const int qb = blockIdx.x;   // query tile
    const int h  = blockIdx.y;   // q head
    const int b  = blockIdx.z;   // batch
    const int kvh = h / (NH / NKV);
    const int tid = threadIdx.x;
    const int tx = tid & 15, ty = tid >> 4;

    // load Q tile, transposed
    for (int idx = tid; idx < BQ * HD / 4; idx += 256) {
        int r = idx >> 5, dq = idx & 31;   // HD/4 = 32 float4 per row
        float4 v4 = *(const float4*)(q + (size_t)(b * SEQ + qb * BQ + r) * HIDDEN + h * HD + dq * 4);
        S->Qt[dq*4+0][r] = v4.x; S->Qt[dq*4+1][r] = v4.y;
        S->Qt[dq*4+2][r] = v4.z; S->Qt[dq*4+3][r] = v4.w;
    }
    if (tid < BQ) { S->Mx[tid] = -1e30f; S->L[tid] = 0.f; }
    __syncthreads();

    float accO[4][8];
    #pragma unroll
    for (int i = 0; i < 4; i++)
        #pragma unroll
        for (int j = 0; j < 8; j++) accO[i][j] = 0.f;

    const float scale = 0.08838834764831845f;  // 1/sqrt(128)
    const int nkv = qb + 1;                    // causal: kv tiles up to diag

    for (int kb = 0; kb < nkv; kb++) {
        // load K (transposed) and V tiles
        for (int idx = tid; idx < BKV * HD / 4; idx += 256) {
            int r = idx >> 5, dq = idx & 31;
            size_t base = (size_t)(b * SEQ + kb * BKV + r) * KVD + kvh * HD + dq * 4;
            float4 k4 = *(const float4*)(k + base);
            S->Kt[dq*4+0][r] = k4.x; S->Kt[dq*4+1][r] = k4.y;
            S->Kt[dq*4+2][r] = k4.z; S->Kt[dq*4+3][r] = k4.w;
            *(float4*)&S->V[r][dq*4] = *(const float4*)(v + base);
        }
        if (tid < BKV) S->Msk[tid] = amask[b * SEQ + kb * BKV + tid];
        __syncthreads();

        // S = Q K^T : each thread 4 rows x 4 cols
        float sc[4][4];
        #pragma unroll
        for (int i = 0; i < 4; i++)
            #pragma unroll
            for (int j = 0; j < 4; j++) sc[i][j] = 0.f;

        for (int d = 0; d < HD; d++) {
            float4 rq = *(const float4*)&S->Qt[d][ty * 4];
            float4 rk = *(const float4*)&S->Kt[d][tx * 4];
            float ra[4] = {rq.x, rq.y, rq.z, rq.w};
            float rb[4] = {rk.x, rk.y, rk.z, rk.w};
            #pragma unroll
            for (int i = 0; i < 4; i++)
                #pragma unroll
                for (int j = 0; j < 4; j++)
                    sc[i][j] = fmaf(ra[i], rb[j], sc[i][j]);
        }

        // scale + mask, stage scores in smem
        #pragma unroll
        for (int i = 0; i < 4; i++) {
            int rg = qb * BQ + ty * 4 + i;
            #pragma unroll
            for (int j = 0; j < 4; j++) {
                int cl = tx * 4 + j;
                int cg = kb * BKV + cl;
                float val = sc[i][j] * scale;
                if (cg > rg || S->Msk[cl] == 0) val = -1e30f;
                S->P[ty*4+i][cl] = val;
            }
        }
        __syncthreads();

        // online softmax: one thread per query row
        if (tid < BQ) {
            float mo = S->Mx[tid], m = mo;
            #pragma unroll 8
            for (int c = 0; c < BKV; c++) m = fmaxf(m, S->P[tid][c]);
            float ls = 0.f;
            #pragma unroll 8
            for (int c = 0; c < BKV; c++) {
                float p = __expf(S->P[tid][c] - m);
                S->P[tid][c] = p;
                ls += p;
            }
            float al = __expf(mo - m);
            S->Alpha[tid] = al;
            S->L[tid] = S->L[tid] * al + ls;
            S->Mx[tid] = m;
        }
        __syncthreads();

        // rescale accumulators, then O += P @ V (4 rows x 8 cols per thread)
        float al[4];
        #pragma unroll
        for (int i = 0; i < 4; i++) al[i] = S->Alpha[ty * 4 + i];
        #pragma unroll
        for (int i = 0; i < 4; i++)
            #pragma unroll
            for (int j = 0; j < 8; j++) accO[i][j] *= al[i];

        for (int kk = 0; kk < BKV; kk++) {
            float pv[4];
            #pragma unroll
            for (int i = 0; i < 4; i++) pv[i] = S->P[ty*4+i][kk];
            float4 v0 = *(const float4*)&S->V[kk][tx*8];
            float4 v1 = *(const float4*)&S->V[kk][tx*8+4];
            float vv[8] = {v0.x, v0.y, v0.z, v0.w, v1.x, v1.y, v1.z, v1.w};
            #pragma unroll
            for (int i = 0; i < 4; i++)
                #pragma unroll
                for (int j = 0; j < 8; j++)
                    accO[i][j] = fmaf(pv[i], vv[j], accO[i][j]);
        }
        __syncthreads();
    }

    // epilogue: normalize and write to [b, s, h*HD + d] layout
    #pragma unroll
    for (int i = 0; i < 4; i++) {
        int r = ty * 4 + i;
        float invl = 1.0f / S->L[r];
        float4 o0 = make_float4(accO[i][0]*invl, accO[i][1]*invl, accO[i][2]*invl, accO[i][3]*invl);
        float4 o1 = make_float4(accO[i][4]*invl, accO[i][5]*invl, accO[i][6]*invl, accO[i][7]*invl);
        float4* op = (float4*)(ao + (size_t)(b * SEQ + qb * BQ + r) * HIDDEN + h * HD + tx * 8);
        op[0] = o0;
        op[1] = o1;
    }
}

// ---------------- launch ----------------------------------------------------
extern "C" void kernel_launch(void* const* d_in, const int* in_sizes, int n_in,
                              void* d_out, int out_size)
{
    const float* hs    = (const float*)d_in[0];
    const int*   amask = (const int*)  d_in[1];
    const float* wq    = (const float*)d_in[2];
    const float* wk    = (const float*)d_in[3];
    const float* wv    = (const float*)d_in[4];
    const float* wo    = (const float*)d_in[5];
    float* out = (float*)d_out;

    float *dq, *dk, *dv, *dao;
    cudaGetSymbolAddress((void**)&dq,  g_q);
    cudaGetSymbolAddress((void**)&dk,  g_k);
    cudaGetSymbolAddress((void**)&dv,  g_v);
    cudaGetSymbolAddress((void**)&dao, g_ao);

    // dynamic smem for gemm: 2 bufs * (128 + 128) rows * 36 floats
    const int gemm_smem = 2 * (GBM + GBN) * GLDW * (int)sizeof(float);
    cudaFuncSetAttribute(gemm_3xtf32, cudaFuncAttributeMaxDynamicSharedMemorySize, gemm_smem);

    // projections (3xTF32 tensor cores)
    gemm_3xtf32<<<dim3(HIDDEN / GBN, MTOT / GBM), 256, gemm_smem>>>(hs, wq, dq, MTOT, HIDDEN, HIDDEN);
    gemm_3xtf32<<<dim3(KVD    / GBN, MTOT / GBM), 256, gemm_smem>>>(hs, wk, dk, MTOT, KVD,    HIDDEN);
    gemm_3xtf32<<<dim3(KVD    / GBN, MTOT / GBM), 256, gemm_smem>>>(hs, wv, dv, MTOT, KVD,    HIDDEN);

    // RoPE on q and k
    rope_kernel<<<MTOT, 64>>>(dq, dk);

    // flash attention (fp32 SIMT — unchanged)
    size_t smb = sizeof(AttnSmem);
    cudaFuncSetAttribute(attn_kernel, cudaFuncAttributeMaxDynamicSharedMemorySize, (int)smb);
    attn_kernel<<<dim3(SEQ / BQ, NH, BATCH), 256, smb>>>(dq, dk, dv, amask, dao);

    // output projection (3xTF32 tensor cores)
    gemm_3xtf32<<<dim3(HIDDEN / GBN, MTOT / GBM), 256, gemm_smem>>>(dao, wo, out, MTOT, HIDDEN, HIDDEN);
}

// round 5
// speedup vs baseline: 1.4703x; 1.2351x over previous
#include <cuda_runtime.h>
#include <cuda_fp16.h>
#include <math.h>
#include <stdint.h>

#define HIDDEN 2048
#define NH 16
#define NKV 4
#define HD 128
#define KVD 512
#define BATCH 2
#define SEQ 2048
#define MTOT (BATCH*SEQ)   // 4096

// ---------------- scratch (static device globals; no allocs allowed) -------
__device__ float g_q [(size_t)MTOT * HIDDEN];
__device__ float g_k [(size_t)MTOT * KVD];
__device__ float g_v [(size_t)MTOT * KVD];
__device__ float g_ao[(size_t)MTOT * HIDDEN];

// fp16 hi/lo split operands (lo scaled by 2048)
__device__ __half g_hsh[(size_t)MTOT * HIDDEN];
__device__ __half g_hsl[(size_t)MTOT * HIDDEN];
__device__ __half g_wqh[(size_t)HIDDEN * HIDDEN];
__device__ __half g_wql[(size_t)HIDDEN * HIDDEN];
__device__ __half g_wkh[(size_t)KVD * HIDDEN];
__device__ __half g_wkl[(size_t)KVD * HIDDEN];
__device__ __half g_wvh[(size_t)KVD * HIDDEN];
__device__ __half g_wvl[(size_t)KVD * HIDDEN];
__device__ __half g_woh[(size_t)HIDDEN * HIDDEN];
__device__ __half g_wol[(size_t)HIDDEN * HIDDEN];
__device__ __half g_aoh[(size_t)MTOT * HIDDEN];
__device__ __half g_aol[(size_t)MTOT * HIDDEN];

#define LO_SCALE 2048.0f
#define LO_INV   (1.0f / 2048.0f)

// ---------------- helpers ---------------------------------------------------
__device__ __forceinline__ uint32_t smem_u32(const void* p) {
    return (uint32_t)__cvta_generic_to_shared(p);
}
__device__ __forceinline__ void cpa16(uint32_t smaddr, const void* g) {
    asm volatile("cp.async.cg.shared.global [%0], [%1], 16;" :: "r"(smaddr), "l"(g));
}
__device__ __forceinline__ void cpa_commit() { asm volatile("cp.async.commit_group;"); }
__device__ __forceinline__ void cpa_wait1()  { asm volatile("cp.async.wait_group 1;"); }
__device__ __forceinline__ void cpa_wait0()  { asm volatile("cp.async.wait_group 0;"); }

__device__ __forceinline__ void ldsm_x4(uint32_t* r, uint32_t addr) {
    asm volatile("ldmatrix.sync.aligned.m8n8.x4.shared.b16 {%0,%1,%2,%3}, [%4];"
                 : "=r"(r[0]), "=r"(r[1]), "=r"(r[2]), "=r"(r[3]) : "r"(addr));
}
__device__ __forceinline__ void mma_f16(float* d, const uint32_t* a, const uint32_t* b) {
    asm volatile(
        "mma.sync.aligned.m16n8k16.row.col.f32.f16.f16.f32 "
        "{%0,%1,%2,%3}, {%4,%5,%6,%7}, {%8,%9}, {%0,%1,%2,%3};"
        : "+f"(d[0]), "+f"(d[1]), "+f"(d[2]), "+f"(d[3])
        : "r"(a[0]), "r"(a[1]), "r"(a[2]), "r"(a[3]), "r"(b[0]), "r"(b[1]));
}

// ---------------- split kernel: fp32 -> (hi, lo*2048) fp16 ------------------
__global__ void split_fp16(const float* __restrict__ in,
                           __half* __restrict__ hi,
                           __half* __restrict__ lo, int n4)
{
    for (int i = blockIdx.x * blockDim.x + threadIdx.x; i < n4; i += gridDim.x * blockDim.x) {
        float4 x = ((const float4*)in)[i];
        __half h0 = __float2half(x.x), h1 = __float2half(x.y);
        __half h2 = __float2half(x.z), h3 = __float2half(x.w);
        __half l0 = __float2half((x.x - __half2float(h0)) * LO_SCALE);
        __half l1 = __float2half((x.y - __half2float(h1)) * LO_SCALE);
        __half l2 = __float2half((x.z - __half2float(h2)) * LO_SCALE);
        __half l3 = __float2half((x.w - __half2float(h3)) * LO_SCALE);
        ushort4 hv = make_ushort4(__half_as_ushort(h0), __half_as_ushort(h1),
                                  __half_as_ushort(h2), __half_as_ushort(h3));
        ushort4 lv = make_ushort4(__half_as_ushort(l0), __half_as_ushort(l1),
                                  __half_as_ushort(l2), __half_as_ushort(l3));
        ((ushort4*)hi)[i] = hv;
        ((ushort4*)lo)[i] = lv;
    }
}

// ============================================================================
// fp16-split GEMM: C[M,N] = A[M,K] * W[N,K]^T, K = 2048
// 128x128x32 block tile, 512 threads (16 warps, 4x4), warp tile 32x32
// 3 MMAs per k16: hi*hi -> acc_h ; hi*lo + lo*hi -> acc_l ; C = acc_h + acc_l/2048
// ============================================================================
#define LDH 40                  // halfs per smem row (32 data + 8 pad)
#define LDB (LDH * 2)           // 80 bytes
#define ARR (128 * LDB)         // 10240 bytes per array
#define BUFB (4 * ARR)          // Ah, Al, Bh, Bl
#define GSM (2 * BUFB)          // 81920 double-buffered

__global__ __launch_bounds__(512) void gemm_fp16x2(
    const __half* __restrict__ Ah_, const __half* __restrict__ Al_,
    const __half* __restrict__ Bh_, const __half* __restrict__ Bl_,
    float* __restrict__ C, int N)
{
    extern __shared__ char dsm[];
    const uint32_t base = smem_u32(dsm);

    const int tid  = threadIdx.x;
    const int warp = tid >> 5, lane = tid & 31;
    const int wr = warp & 3, wc = warp >> 2;     // 4x4 warp grid
    const int row0 = blockIdx.y * 128;
    const int col0 = blockIdx.x * 128;

    const char* src[4] = {
        (const char*)(Ah_ + (size_t)row0 * HIDDEN),
        (const char*)(Al_ + (size_t)row0 * HIDDEN),
        (const char*)(Bh_ + (size_t)col0 * HIDDEN),
        (const char*)(Bl_ + (size_t)col0 * HIDDEN)
    };

    const int nChunk = HIDDEN / 32;   // 64

    // each thread: one 16B chunk per array per tile
    const int lr = tid >> 2;          // 0..127 row
    const int lc = tid & 3;           // 0..3   16B chunk within 64B row
    auto loadTile = [&](int t, int buf) {
        #pragma unroll
        for (int a = 0; a < 4; a++) {
            cpa16(base + buf * BUFB + a * ARR + lr * LDB + lc * 16,
                  src[a] + ((size_t)lr * HIDDEN + t * 32) * 2 + lc * 16);
        }
        cpa_commit();
    };

    float acch[2][4][4], accl[2][4][4];
    #pragma unroll
    for (int mi = 0; mi < 2; mi++)
        #pragma unroll
        for (int ni = 0; ni < 4; ni++)
            #pragma unroll
            for (int r = 0; r < 4; r++) { acch[mi][ni][r] = 0.f; accl[mi][ni][r] = 0.f; }

    // ldmatrix lane-address offsets (bytes, within an array)
    const uint32_t aoffA = (uint32_t)((wr * 32 + (lane & 15)) * LDB + ((lane >> 4) << 3) * 2);
    const uint32_t aoffB = (uint32_t)((wc * 32 + ((lane >> 4) << 3) + (lane & 7)) * LDB
                                      + (((lane >> 3) & 1) << 3) * 2);

    loadTile(0, 0);

    for (int t = 0; t < nChunk; t++) {
        const int buf = t & 1;
        if (t + 1 < nChunk) { loadTile(t + 1, buf ^ 1); cpa_wait1(); }
        else                { cpa_wait0(); }
        __syncthreads();

        const uint32_t bo = base + buf * BUFB;

        #pragma unroll
        for (int ks = 0; ks < 2; ks++) {
            const uint32_t kb = (uint32_t)(ks * 32);   // 16 halfs = 32 bytes

            uint32_t ah[2][4], al[2][4];
            ldsm_x4(ah[0], bo + 0 * ARR + aoffA + kb);
            ldsm_x4(ah[1], bo + 0 * ARR + aoffA + kb + 16 * LDB);
            ldsm_x4(al[0], bo + 1 * ARR + aoffA + kb);
            ldsm_x4(al[1], bo + 1 * ARR + aoffA + kb + 16 * LDB);

            uint32_t bh[4][2], bl[4][2], tmp[4];
            ldsm_x4(tmp, bo + 2 * ARR + aoffB + kb);
            bh[0][0] = tmp[0]; bh[0][1] = tmp[1]; bh[1][0] = tmp[2]; bh[1][1] = tmp[3];
            ldsm_x4(tmp, bo + 2 * ARR + aoffB + kb + 16 * LDB);
            bh[2][0] = tmp[0]; bh[2][1] = tmp[1]; bh[3][0] = tmp[2]; bh[3][1] = tmp[3];
            ldsm_x4(tmp, bo + 3 * ARR + aoffB + kb);
            bl[0][0] = tmp[0]; bl[0][1] = tmp[1]; bl[1][0] = tmp[2]; bl[1][1] = tmp[3];
            ldsm_x4(tmp, bo + 3 * ARR + aoffB + kb + 16 * LDB);
            bl[2][0] = tmp[0]; bl[2][1] = tmp[1]; bl[3][0] = tmp[2]; bl[3][1] = tmp[3];

            #pragma unroll
            for (int mi = 0; mi < 2; mi++)
                #pragma unroll
                for (int ni = 0; ni < 4; ni++) {
                    mma_f16(acch[mi][ni], ah[mi], bh[ni]);   // hi*hi
                    mma_f16(accl[mi][ni], ah[mi], bl[ni]);   // hi*lo'
                    mma_f16(accl[mi][ni], al[mi], bh[ni]);   // lo'*hi
                }
        }
        __syncthreads();
    }

    // epilogue: C = acc_h + acc_l / 2048
    #pragma unroll
    for (int mi = 0; mi < 2; mi++)
        #pragma unroll
        for (int ni = 0; ni < 4; ni++) {
            const int row = row0 + wr * 32 + mi * 16 + (lane >> 2);
            const int col = col0 + wc * 32 + ni * 8 + 2 * (lane & 3);
            float v0 = acch[mi][ni][0] + accl[mi][ni][0] * LO_INV;
            float v1 = acch[mi][ni][1] + accl[mi][ni][1] * LO_INV;
            float v2 = acch[mi][ni][2] + accl[mi][ni][2] * LO_INV;
            float v3 = acch[mi][ni][3] + accl[mi][ni][3] * LO_INV;
            *(float2*)(C + (size_t)row * N + col)       = make_float2(v0, v1);
            *(float2*)(C + (size_t)(row + 8) * N + col) = make_float2(v2, v3);
        }
}

// ---------------- RoPE (in-place on q [MTOT,2048] and k [MTOT,512]) --------
__global__ void rope_kernel(float* __restrict__ q, float* __restrict__ k)
{
    const int bs  = blockIdx.x;
    const int pos = bs % SEQ;
    const int i   = threadIdx.x;       // 0..63
    float inv = powf(10000.0f, -(float)i / 64.0f);
    float ang = (float)pos * inv;
    float s, c;
    sincosf(ang, &s, &c);

    #pragma unroll
    for (int h = 0; h < NH; h++) {
        float* p = q + (size_t)bs * HIDDEN + h * HD;
        float a = p[i], b2 = p[i + 64];
        p[i]      = a * c - b2 * s;
        p[i + 64] = b2 * c + a * s;
    }
    #pragma unroll
    for (int h = 0; h < NKV; h++) {
        float* p = k + (size_t)bs * KVD + h * HD;
        float a = p[i], b2 = p[i + 64];
        p[i]      = a * c - b2 * s;
        p[i + 64] = b2 * c + a * s;
    }
}

// ---------------- Flash attention (causal, GQA), fp32 ----------------------
#define BQ 64
#define BKV 64

struct AttnSmem {
    float Qt[HD][BQ];
    float Kt[HD][BKV];
    float V [BKV][HD];
    float P [BQ][BKV];
    float Mx[BQ];
    float L [BQ];
    float Alpha[BQ];
    int   Msk[BKV];
};

__global__ __launch_bounds__(256) void attn_kernel(
    const float* __restrict__ q, const float* __restrict__ k,
    const float* __restrict__ v, const int* __restrict__ amask,
    float* __restrict__ ao)
{
    extern __shared__ char smraw[];
    AttnSmem* S = reinterpret_cast<AttnSmem*>(smraw);

    const int qb = blockIdx.x;
    const int h  = blockIdx.y;
    const int b  = blockIdx.z;
    const int kvh = h / (NH / NKV);
    const int tid = threadIdx.x;
    const int tx = tid & 15, ty = tid >> 4;

    for (int idx = tid; idx < BQ * HD / 4; idx += 256) {
        int r = idx >> 5, dq = idx & 31;
        float4 v4 = *(const float4*)(q + (size_t)(b * SEQ + qb * BQ + r) * HIDDEN + h * HD + dq * 4);
        S->Qt[dq*4+0][r] = v4.x; S->Qt[dq*4+1][r] = v4.y;
        S->Qt[dq*4+2][r] = v4.z; S->Qt[dq*4+3][r] = v4.w;
    }
    if (tid < BQ) { S->Mx[tid] = -1e30f; S->L[tid] = 0.f; }
    __syncthreads();

    float accO[4][8];
    #pragma unroll
    for (int i = 0; i < 4; i++)
        #pragma unroll
        for (int j = 0; j < 8; j++) accO[i][j] = 0.f;

    const float scale = 0.08838834764831845f;
    const int nkv = qb + 1;

    for (int kb = 0; kb < nkv; kb++) {
        for (int idx = tid; idx < BKV * HD / 4; idx += 256) {
            int r = idx >> 5, dq = idx & 31;
            size_t basea = (size_t)(b * SEQ + kb * BKV + r) * KVD + kvh * HD + dq * 4;
            float4 k4 = *(const float4*)(k + basea);
            S->Kt[dq*4+0][r] = k4.x; S->Kt[dq*4+1][r] = k4.y;
            S->Kt[dq*4+2][r] = k4.z; S->Kt[dq*4+3][r] = k4.w;
            *(float4*)&S->V[r][dq*4] = *(const float4*)(v + basea);
        }
        if (tid < BKV) S->Msk[tid] = amask[b * SEQ + kb * BKV + tid];
        __syncthreads();

        float sc[4][4];
        #pragma unroll
        for (int i = 0; i < 4; i++)
            #pragma unroll
            for (int j = 0; j < 4; j++) sc[i][j] = 0.f;

        for (int d = 0; d < HD; d++) {
            float4 rq = *(const float4*)&S->Qt[d][ty * 4];
            float4 rk = *(const float4*)&S->Kt[d][tx * 4];
            float ra[4] = {rq.x, rq.y, rq.z, rq.w};
            float rb[4] = {rk.x, rk.y, rk.z, rk.w};
            #pragma unroll
            for (int i = 0; i < 4; i++)
                #pragma unroll
                for (int j = 0; j < 4; j++)
                    sc[i][j] = fmaf(ra[i], rb[j], sc[i][j]);
        }

        #pragma unroll
        for (int i = 0; i < 4; i++) {
            int rg = qb * BQ + ty * 4 + i;
            #pragma unroll
            for (int j = 0; j < 4; j++) {
                int cl = tx * 4 + j;
                int cg = kb * BKV + cl;
                float val = sc[i][j] * scale;
                if (cg > rg || S->Msk[cl] == 0) val = -1e30f;
                S->P[ty*4+i][cl] = val;
            }
        }
        __syncthreads();

        if (tid < BQ) {
            float mo = S->Mx[tid], m = mo;
            #pragma unroll 8
            for (int c = 0; c < BKV; c++) m = fmaxf(m, S->P[tid][c]);
            float ls = 0.f;
            #pragma unroll 8
            for (int c = 0; c < BKV; c++) {
                float p = __expf(S->P[tid][c] - m);
                S->P[tid][c] = p;
                ls += p;
            }
            float al = __expf(mo - m);
            S->Alpha[tid] = al;
            S->L[tid] = S->L[tid] * al + ls;
            S->Mx[tid] = m;
        }
        __syncthreads();

        float al[4];
        #pragma unroll
        for (int i = 0; i < 4; i++) al[i] = S->Alpha[ty * 4 + i];
        #pragma unroll
        for (int i = 0; i < 4; i++)
            #pragma unroll
            for (int j = 0; j < 8; j++) accO[i][j] *= al[i];

        for (int kk = 0; kk < BKV; kk++) {
            float pv[4];
            #pragma unroll
            for (int i = 0; i < 4; i++) pv[i] = S->P[ty*4+i][kk];
            float4 v0 = *(const float4*)&S->V[kk][tx*8];
            float4 v1 = *(const float4*)&S->V[kk][tx*8+4];
            float vv[8] = {v0.x, v0.y, v0.z, v0.w, v1.x, v1.y, v1.z, v1.w};
            #pragma unroll
            for (int i = 0; i < 4; i++)
                #pragma unroll
                for (int j = 0; j < 8; j++)
                    accO[i][j] = fmaf(pv[i], vv[j], accO[i][j]);
        }
        __syncthreads();
    }

    #pragma unroll
    for (int i = 0; i < 4; i++) {
        int r = ty * 4 + i;
        float invl = 1.0f / S->L[r];
        float4 o0 = make_float4(accO[i][0]*invl, accO[i][1]*invl, accO[i][2]*invl, accO[i][3]*invl);
        float4 o1 = make_float4(accO[i][4]*invl, accO[i][5]*invl, accO[i][6]*invl, accO[i][7]*invl);
        float4* op = (float4*)(ao + (size_t)(b * SEQ + qb * BQ + r) * HIDDEN + h * HD + tx * 8);
        op[0] = o0;
        op[1] = o1;
    }
}

// ---------------- launch ----------------------------------------------------
extern "C" void kernel_launch(void* const* d_in, const int* in_sizes, int n_in,
                              void* d_out, int out_size)
{
    const float* hs    = (const float*)d_in[0];
    const int*   amask = (const int*)  d_in[1];
    const float* wq    = (const float*)d_in[2];
    const float* wk    = (const float*)d_in[3];
    const float* wv    = (const float*)d_in[4];
    const float* wo    = (const float*)d_in[5];
    float* out = (float*)d_out;

    float *dq, *dk, *dv, *dao;
    cudaGetSymbolAddress((void**)&dq,  g_q);
    cudaGetSymbolAddress((void**)&dk,  g_k);
    cudaGetSymbolAddress((void**)&dv,  g_v);
    cudaGetSymbolAddress((void**)&dao, g_ao);

    __half *hsh, *hsl, *wqh, *wql, *wkh, *wkl, *wvh, *wvl, *woh, *wol, *aoh, *aol;
    cudaGetSymbolAddress((void**)&hsh, g_hsh); cudaGetSymbolAddress((void**)&hsl, g_hsl);
    cudaGetSymbolAddress((void**)&wqh, g_wqh); cudaGetSymbolAddress((void**)&wql, g_wql);
    cudaGetSymbolAddress((void**)&wkh, g_wkh); cudaGetSymbolAddress((void**)&wkl, g_wkl);
    cudaGetSymbolAddress((void**)&wvh, g_wvh); cudaGetSymbolAddress((void**)&wvl, g_wvl);
    cudaGetSymbolAddress((void**)&woh, g_woh); cudaGetSymbolAddress((void**)&wol, g_wol);
    cudaGetSymbolAddress((void**)&aoh, g_aoh); cudaGetSymbolAddress((void**)&aol, g_aol);

    cudaFuncSetAttribute(gemm_fp16x2, cudaFuncAttributeMaxDynamicSharedMemorySize, GSM);

    // split inputs into fp16 hi/lo
    split_fp16<<<1024, 256>>>(hs, hsh, hsl, MTOT * HIDDEN / 4);
    split_fp16<<<1024, 256>>>(wq, wqh, wql, HIDDEN * HIDDEN / 4);
    split_fp16<<<512,  256>>>(wk, wkh, wkl, KVD * HIDDEN / 4);
    split_fp16<<<512,  256>>>(wv, wvh, wvl, KVD * HIDDEN / 4);
    split_fp16<<<1024, 256>>>(wo, woh, wol, HIDDEN * HIDDEN / 4);

    // projections (fp16-split tensor cores)
    gemm_fp16x2<<<dim3(HIDDEN / 128, MTOT / 128), 512, GSM>>>(hsh, hsl, wqh, wql, dq, HIDDEN);
    gemm_fp16x2<<<dim3(KVD    / 128, MTOT / 128), 512, GSM>>>(hsh, hsl, wkh, wkl, dk, KVD);
    gemm_fp16x2<<<dim3(KVD    / 128, MTOT / 128), 512, GSM>>>(hsh, hsl, wvh, wvl, dv, KVD);

    // RoPE on q and k
    rope_kernel<<<MTOT, 64>>>(dq, dk);

    // flash attention (fp32 SIMT — unchanged)
    size_t smb = sizeof(AttnSmem);
    cudaFuncSetAttribute(attn_kernel, cudaFuncAttributeMaxDynamicSharedMemorySize, (int)smb);
    attn_kernel<<<dim3(SEQ / BQ, NH, BATCH), 256, smb>>>(dq, dk, dv, amask, dao);

    // split attention output, then O-projection
    split_fp16<<<1024, 256>>>(dao, aoh, aol, MTOT * HIDDEN / 4);
    gemm_fp16x2<<<dim3(HIDDEN / 128, MTOT / 128), 512, GSM>>>(aoh, aol, woh, wol, out, HIDDEN);
}